// round 4
// baseline (speedup 1.0000x reference)
#include <cuda_runtime.h>

// Problem constants (fixed by this problem instance)
#define NN 16000
#define EE 48000
#define FF 32000
#define GG 32
#define DD 64
#define BB 32
#define MM (NN + EE + FF)
#define HID 256
#define NC 10
#define FLATW (BB * DD)   // 2048

// ecc kernel tiling
#define CS    384         // items per block chunk
#define ECC_Y 4           // item lanes per block (private band copies)
#define TPB   256         // 64 dims x 4 lanes

// Device scratch (no allocations allowed)
__device__ float g_nh[NN * DD];        // node heights [N, 64]
__device__ int4  g_items[MM];          // sorted items {i0,i1,i2, w_bits(sign=contrib sign)}
__device__ int   g_hist[GG];
__device__ int   g_off[GG + 1];
__device__ int   g_cursor[GG];
__device__ float g_acc[GG * BB * DD];  // band partial sums (signed)
__device__ float g_stp[GG * BB * DD];  // step counters (signed)
__device__ float g_flat[GG * FLATW];

// ---------------------------------------------------------------------------
__global__ void k_zero() {
    int t = blockIdx.x * blockDim.x + threadIdx.x;
    if (t < GG * BB * DD) {
        g_acc[t] = 0.f;
        g_stp[t] = 0.f;
    } else {
        int u = t - GG * BB * DD;
        if (u < GG) g_hist[u] = 0;
    }
}

// nh[n,d] = node_weights[n] * sum_k x[n,k] * v[k,d]
__global__ void k_nh(const float* __restrict__ x, const float* __restrict__ nw,
                     const float* __restrict__ v) {
    int t = blockIdx.x * blockDim.x + threadIdx.x;
    if (t >= NN * DD) return;
    int n = t >> 6, d = t & 63;
    float w = nw[n];
    float acc = x[n * 3 + 0] * v[0 * DD + d]
              + x[n * 3 + 1] * v[1 * DD + d]
              + x[n * 3 + 2] * v[2 * DD + d];
    g_nh[t] = acc * w;
}

__device__ __forceinline__ int item_graph(int t, const int* ei,
                                          const int* fc, const int* bid) {
    if (t < NN)            return bid[t];
    else if (t < NN + EE)  return bid[ei[t - NN]];
    else                   return bid[fc[t - NN - EE]];
}

__global__ void k_hist(const int* __restrict__ ei, const int* __restrict__ fc,
                       const int* __restrict__ bid) {
    __shared__ int sh[GG];
    int tid = threadIdx.x;
    if (tid < GG) sh[tid] = 0;
    __syncthreads();
    int t = blockIdx.x * blockDim.x + tid;
    if (t < MM) atomicAdd(&sh[item_graph(t, ei, fc, bid)], 1);
    __syncthreads();
    if (tid < GG && sh[tid] > 0) atomicAdd(&g_hist[tid], sh[tid]);
}

__global__ void k_prefix() {
    int s = 0;
    for (int g = 0; g < GG; g++) {
        g_off[g] = s;
        g_cursor[g] = s;
        s += g_hist[g];
    }
    g_off[GG] = s;
}

__global__ void k_scatter(const int* __restrict__ ei, const int* __restrict__ fc,
                          const int* __restrict__ bid,
                          const float* __restrict__ ew, const float* __restrict__ fw) {
    __shared__ int scnt[GG];
    __shared__ int sbase[GG];
    int tid = threadIdx.x;
    if (tid < GG) scnt[tid] = 0;
    __syncthreads();
    int t = blockIdx.x * blockDim.x + tid;
    int g = 0, lr = 0;
    int4 it = make_int4(0, 0, 0, 0);
    bool valid = (t < MM);
    if (valid) {
        if (t < NN) {
            g = bid[t];
            it = make_int4(t, t, t, __float_as_int(1.0f));            // node: sign +
        } else if (t < NN + EE) {
            int e = t - NN;
            int a = ei[e], b = ei[EE + e];
            g = bid[a];
            it = make_int4(a, b, a, __float_as_int(-ew[e]));          // edge: sign -
        } else {
            int q = t - NN - EE;
            int a = fc[q], b = fc[FF + q], c = fc[2 * FF + q];
            g = bid[a];
            it = make_int4(a, b, c, __float_as_int(fw[q]));           // face: sign +
        }
        lr = atomicAdd(&scnt[g], 1);
    }
    __syncthreads();
    if (tid < GG && scnt[tid] > 0) sbase[tid] = atomicAdd(&g_cursor[tid], scnt[tid]);
    __syncthreads();
    if (valid) g_items[sbase[g] + lr] = it;
}

// Main ECC kernel: banded sigmoid + step counters, per-graph smem accumulation.
__global__ void k_ecc() {
    int g = blockIdx.y;
    int s0 = g_off[g], s1 = g_off[g + 1];
    int start = s0 + blockIdx.x * CS;
    if (start >= s1) return;
    int end = min(start + CS, s1);

    __shared__ float tab[769];                 // sigmoid((200/31)*m), m in [-3,3], 128/unit
    __shared__ float band[ECC_Y * BB * DD];    // private copies, exclusive (lane,dim) columns
    __shared__ float stp[BB * DD];             // single copy, smem atomics (1 op/item-dim)

    int tid = threadIdx.x;
    int d = tid & 63, y = tid >> 6;

    for (int i = tid; i < 769; i += TPB) {
        float m = (float)i * (1.0f / 128.0f) - 3.0f;
        tab[i] = 1.0f / (1.0f + __expf(-(200.0f / 31.0f) * m));
    }
    for (int i = tid; i < ECC_Y * BB * DD; i += TPB) band[i] = 0.f;
    for (int i = tid; i < BB * DD; i += TPB) stp[i] = 0.f;
    __syncthreads();

    float* bcol = band + y * (BB * DD) + d;

    for (int i = start + y; i < end; i += ECC_Y) {
        int4 it = g_items[i];                  // broadcast across the 64 dim-threads
        float s  = (it.w < 0) ? -1.f : 1.f;    // works for -0.0 too (0x80000000 < 0)
        float wa = fabsf(__int_as_float(it.w));
        float h0 = g_nh[it.x * DD + d];
        float h1 = g_nh[it.y * DD + d];
        float h2 = g_nh[it.z * DD + d];
        float h  = fmaxf(h0, fmaxf(h1, h2)) * wa;

        float f  = (h + 1.0f) * 15.5f;         // bump coordinate of h
        int blo  = (int)ceilf(f - 2.8f);       // below band: sigmoid < 1.5e-8 -> drop
        int bhiR = (int)ceilf(f + 2.8f);       // at/above: sigmoid == 1.0 (fp32) -> count
        int lo = max(blo, 0), hi = min(bhiR, 32);

        #pragma unroll 1
        for (int b = lo; b < hi; b++) {
            float ti = ((float)b - f + 3.0f) * 128.0f;   // in (25.6, 742.4)
            int   ix = (int)ti;
            float fr = ti - (float)ix;
            float t0 = tab[ix];
            float sg = t0 + fr * (tab[ix + 1] - t0);
            bcol[b * DD] += s * sg;            // conflict-free exclusive RMW
        }
        int je = min(max(bhiR, 0), 32);
        if (je < 32) atomicAdd(&stp[je * DD + d], s);
    }
    __syncthreads();

    for (int i = tid; i < BB * DD; i += TPB) {
        float v = band[i] + band[BB * DD + i] + band[2 * BB * DD + i] + band[3 * BB * DD + i];
        atomicAdd(&g_acc[g * BB * DD + i], v);
        float sv = stp[i];
        if (sv != 0.f) atomicAdd(&g_stp[g * BB * DD + i], sv);
    }
}

// ecc[g,b,d] = band[g,b,d] + prefix_{b' <= b} step[g,b',d]; write flat.
__global__ void k_fin(float* __restrict__ out, int flat_off) {
    int g = blockIdx.x;
    int d = threadIdx.x;  // 64
    float run = 0.f;
    #pragma unroll
    for (int b = 0; b < BB; b++) {
        run += g_stp[(g * BB + b) * DD + d];
        float v = g_acc[(g * BB + b) * DD + d] + run;
        g_flat[g * FLATW + b * DD + d] = v;
        if (flat_off >= 0) out[flat_off + g * FLATW + b * DD + d] = v;
    }
}

// h = relu(flat @ W1^T + b1); logits = h @ W2^T + b2
__global__ void k_mlp(const float* __restrict__ W1, const float* __restrict__ b1,
                      const float* __restrict__ W2, const float* __restrict__ b2,
                      float* __restrict__ out, int logit_off) {
    __shared__ float sf[FLATW];
    __shared__ float sh[HID];
    int g = blockIdx.x;
    int tid = threadIdx.x;  // 256 = HID
    for (int i = tid; i < FLATW; i += HID) sf[i] = g_flat[g * FLATW + i];
    __syncthreads();
    float acc = b1[tid];
    const float4* w = (const float4*)(W1 + tid * FLATW);
    #pragma unroll 8
    for (int k = 0; k < FLATW / 4; k++) {
        float4 wv = w[k];
        acc += wv.x * sf[4 * k] + wv.y * sf[4 * k + 1]
             + wv.z * sf[4 * k + 2] + wv.w * sf[4 * k + 3];
    }
    sh[tid] = fmaxf(acc, 0.f);
    __syncthreads();
    if (tid < NC && logit_off >= 0) {
        float a2 = b2[tid];
        #pragma unroll 8
        for (int k = 0; k < HID; k++) a2 += sh[k] * W2[tid * HID + k];
        out[logit_off + g * NC + tid] = a2;
    }
}

// ---------------------------------------------------------------------------
extern "C" void kernel_launch(void* const* d_in, const int* in_sizes, int n_in,
                              void* d_out, int out_size) {
    const float* x   = (const float*)d_in[0];
    const float* nw  = (const float*)d_in[1];
    const float* ew  = (const float*)d_in[2];
    const float* fw  = (const float*)d_in[3];
    const float* v   = (const float*)d_in[4];
    const float* W1  = (const float*)d_in[5];
    const float* b1  = (const float*)d_in[6];
    const float* W2  = (const float*)d_in[7];
    const float* b2  = (const float*)d_in[8];
    const int*   ei  = (const int*)d_in[9];    // int32: JAX x64-disabled downcast
    const int*   fc  = (const int*)d_in[10];
    const int*   bid = (const int*)d_in[11];
    float* out = (float*)d_out;

    // Output layout: reference returns (logits[32,10], flat[32,2048]).
    int flat_off, logit_off;
    if (out_size >= GG * NC + GG * FLATW) { logit_off = 0; flat_off = GG * NC; }
    else if (out_size >= GG * FLATW)      { logit_off = -1; flat_off = 0; }
    else                                  { logit_off = 0; flat_off = -1; }

    k_zero<<<(2 * GG * BB * DD + GG + 255) / 256, 256>>>();
    k_nh<<<(NN * DD + 255) / 256, 256>>>(x, nw, v);
    k_hist<<<(MM + 255) / 256, 256>>>(ei, fc, bid);
    k_prefix<<<1, 1>>>();
    k_scatter<<<(MM + 255) / 256, 256>>>(ei, fc, bid, ew, fw);

    dim3 gecc((MM + CS - 1) / CS, GG);   // safe upper bound; empty chunks exit immediately
    k_ecc<<<gecc, TPB>>>();

    k_fin<<<GG, DD>>>(out, flat_off);
    k_mlp<<<GG, HID>>>(W1, b1, W2, b2, out, logit_off);
}

// round 7
// speedup vs baseline: 1.6316x; 1.6316x over previous
#include <cuda_runtime.h>

// Problem constants
#define NN 16000
#define EE 48000
#define FF 32000
#define GG 32
#define DD 64
#define BB 32
#define MM (NN + EE + FF)
#define HID 256
#define NC 10
#define FLATW (BB * DD)   // 2048

// ecc tiling
#define CS    128          // items per chunk
#define ECC_Y 4            // item lanes per block
#define TPB   256          // 64 dims x 4 lanes
#define MAXCH ((MM + CS - 1) / CS + GG)   // 782 upper bound on chunks
#define TABN  516          // sigmoid table entries (need idx 0..512)

// Device scratch
__device__ float g_nh[NN * DD];
__device__ int4  g_items[MM];
__device__ int   g_hist[GG];
__device__ int   g_off[GG + 1];
__device__ int   g_cursor[GG];
__device__ int   g_nch;
__device__ int4  g_chunks[MAXCH];      // {graph, start, end, 0}
__device__ float g_acc[GG * BB * DD];
__device__ float g_stp[GG * BB * DD];

// ---------------------------------------------------------------------------
// Fused: nh compute + accumulator zero + graph histogram (independent ranges)
#define NH_B ((NN * DD + 255) / 256)          // 4000
#define Z_B  ((2 * GG * BB * DD + GG + 255) / 256)  // 513
#define H_B  ((MM + 255) / 256)               // 375

__global__ void k_init(const float* __restrict__ x, const float* __restrict__ nw,
                       const float* __restrict__ v,
                       const int* __restrict__ ei, const int* __restrict__ fc,
                       const int* __restrict__ bid) {
    __shared__ int sh[GG];
    int b = blockIdx.x, tid = threadIdx.x;
    if (b < NH_B) {
        int t = b * 256 + tid;
        if (t < NN * DD) {
            int n = t >> 6, d = t & 63;
            float acc = x[n * 3 + 0] * v[0 * DD + d]
                      + x[n * 3 + 1] * v[1 * DD + d]
                      + x[n * 3 + 2] * v[2 * DD + d];
            g_nh[t] = acc * nw[n];
        }
    } else if (b < NH_B + Z_B) {
        int t = (b - NH_B) * 256 + tid;
        if (t < GG * BB * DD) { g_acc[t] = 0.f; g_stp[t] = 0.f; }
        else { int u = t - GG * BB * DD; if (u < GG) g_hist[u] = 0; }
    } else {
        if (tid < GG) sh[tid] = 0;
        __syncthreads();
        int t = (b - NH_B - Z_B) * 256 + tid;
        if (t < MM) {
            int g;
            if (t < NN)           g = bid[t];
            else if (t < NN + EE) g = bid[ei[t - NN]];
            else                  g = bid[fc[t - NN - EE]];
            atomicAdd(&sh[g], 1);
        }
        __syncthreads();
        if (tid < GG && sh[tid] > 0) atomicAdd(&g_hist[tid], sh[tid]);
    }
}

// Warp-parallel prefix + chunk-table builder (1 block, 32 threads)
__global__ void k_prefix() {
    int g = threadIdx.x;
    int cnt = g_hist[g];
    int v = cnt;
    #pragma unroll
    for (int s = 1; s < 32; s <<= 1) {
        int t = __shfl_up_sync(0xFFFFFFFFu, v, s);
        if (g >= s) v += t;
    }
    int off = v - cnt;
    g_off[g] = off;
    g_cursor[g] = off;
    if (g == 31) g_off[GG] = v;

    int nch = (cnt + CS - 1) / CS;
    int c = nch;
    #pragma unroll
    for (int s = 1; s < 32; s <<= 1) {
        int t = __shfl_up_sync(0xFFFFFFFFu, c, s);
        if (g >= s) c += t;
    }
    int cbase = c - nch;
    if (g == 31) g_nch = c;
    for (int j = 0; j < nch; j++) {
        int st = off + j * CS;
        int en = min(st + CS, off + cnt);
        g_chunks[cbase + j] = make_int4(g, st, en, 0);
    }
}

__global__ void k_scatter(const int* __restrict__ ei, const int* __restrict__ fc,
                          const int* __restrict__ bid,
                          const float* __restrict__ ew, const float* __restrict__ fw) {
    __shared__ int scnt[GG];
    __shared__ int sbase[GG];
    int tid = threadIdx.x;
    if (tid < GG) scnt[tid] = 0;
    __syncthreads();
    int t = blockIdx.x * blockDim.x + tid;
    int g = 0, lr = 0;
    int4 it = make_int4(0, 0, 0, 0);
    bool valid = (t < MM);
    if (valid) {
        if (t < NN) {
            g = bid[t];
            it = make_int4(t, t, t, __float_as_int(1.0f));
        } else if (t < NN + EE) {
            int e = t - NN;
            int a = ei[e], b = ei[EE + e];
            g = bid[a];
            it = make_int4(a, b, a, __float_as_int(-ew[e]));
        } else {
            int q = t - NN - EE;
            int a = fc[q], b = fc[FF + q], c = fc[2 * FF + q];
            g = bid[a];
            it = make_int4(a, b, c, __float_as_int(fw[q]));
        }
        lr = atomicAdd(&scnt[g], 1);
    }
    __syncthreads();
    if (tid < GG && scnt[tid] > 0) sbase[tid] = atomicAdd(&g_cursor[tid], scnt[tid]);
    __syncthreads();
    if (valid) g_items[sbase[g] + lr] = it;
}

// Main ECC kernel: exact chunk grid, fixed-4 unrolled band, float2 table.
__global__ void __launch_bounds__(TPB) k_ecc() {
    __shared__ float2 tab[TABN];               // {sigmoid, delta-to-next}
    __shared__ float band[ECC_Y * BB * DD];    // private (lane,dim) columns
    __shared__ float stp[BB * DD];

    int bidx = blockIdx.x;
    if (bidx >= g_nch) return;
    int4 ck = g_chunks[bidx];
    int g = ck.x, start = ck.y, end = ck.z;

    int tid = threadIdx.x;
    int d = tid & 63, y = tid >> 6;

    for (int i = tid; i < TABN; i += TPB) {
        // m in [-2, 2+], 128 steps/unit; argument = (200/31)*m
        float m0 = (float)i * (1.0f / 128.0f) - 2.0f;
        float m1 = m0 + (1.0f / 128.0f);
        float s0 = 1.0f / (1.0f + __expf(-(200.0f / 31.0f) * m0));
        float s1 = 1.0f / (1.0f + __expf(-(200.0f / 31.0f) * m1));
        tab[i] = make_float2(s0, s1 - s0);
    }
    for (int i = tid; i < ECC_Y * BB * DD; i += TPB) band[i] = 0.f;
    for (int i = tid; i < BB * DD; i += TPB) stp[i] = 0.f;
    __syncthreads();

    float* bcol = band + y * (BB * DD) + d;

    for (int i = start + y; i < end; i += ECC_Y) {
        int4 it = g_items[i];                  // broadcast across 64 dim-threads
        float s  = (it.w < 0) ? -1.f : 1.f;
        float wa = fabsf(__int_as_float(it.w));
        float h0 = g_nh[it.x * DD + d];
        float h1 = g_nh[it.y * DD + d];
        float h2 = g_nh[it.z * DD + d];
        float h  = fmaxf(h0, fmaxf(h1, h2)) * wa;

        float f   = (h + 1.0f) * 15.5f;        // bump coordinate
        int   blo = (int)ceilf(f - 2.0f);      // band = exactly {blo..blo+3}

        #pragma unroll
        for (int k = 0; k < 4; k++) {
            int b = blo + k;
            if (b >= 0 && b < BB) {
                float ti = ((float)b - f + 2.0f) * 128.0f;   // in [0, 512]
                int   ix = (int)ti;
                float fr = ti - (float)ix;
                float2 tv = tab[ix];
                bcol[b * DD] += s * (tv.x + fr * tv.y);      // conflict-free RMW
            }
        }
        int je = min(max(blo + 4, 0), BB);     // bumps >= je saturate to 1.0
        if (je < BB) atomicAdd(&stp[je * DD + d], s);
    }
    __syncthreads();

    for (int i = tid; i < BB * DD; i += TPB) {
        float v = band[i] + band[BB * DD + i] + band[2 * BB * DD + i] + band[3 * BB * DD + i];
        atomicAdd(&g_acc[g * BB * DD + i], v);
        float sv = stp[i];
        if (sv != 0.f) atomicAdd(&g_stp[g * BB * DD + i], sv);
    }
}

// Fused finalize (suffix/prefix of step counters) + MLP. grid=32, 256 threads.
__global__ void k_tail(const float* __restrict__ W1, const float* __restrict__ b1,
                       const float* __restrict__ W2, const float* __restrict__ b2,
                       float* __restrict__ out, int flat_off, int logit_off) {
    __shared__ float sf[FLATW];
    __shared__ float ss[4 * DD];
    __shared__ float sh[HID];
    int g = blockIdx.x, tid = threadIdx.x;
    int d = tid & 63, q = tid >> 6;            // q: 8 consecutive b's each

    float vals[8];
    float run = 0.f;
    #pragma unroll
    for (int k = 0; k < 8; k++) {
        int b = q * 8 + k;
        run += g_stp[(g * BB + b) * DD + d];
        vals[k] = run;
    }
    ss[q * DD + d] = run;
    __syncthreads();
    float offp = 0.f;
    for (int r = 0; r < q; r++) offp += ss[r * DD + d];
    #pragma unroll
    for (int k = 0; k < 8; k++) {
        int b = q * 8 + k;
        float v = g_acc[(g * BB + b) * DD + d] + offp + vals[k];
        sf[b * DD + d] = v;
        if (flat_off >= 0) out[flat_off + g * FLATW + b * DD + d] = v;
    }
    __syncthreads();

    float acc = b1[tid];
    const float4* w = (const float4*)(W1 + tid * FLATW);
    #pragma unroll 8
    for (int k = 0; k < FLATW / 4; k++) {
        float4 wv = w[k];
        acc += wv.x * sf[4 * k] + wv.y * sf[4 * k + 1]
             + wv.z * sf[4 * k + 2] + wv.w * sf[4 * k + 3];
    }
    sh[tid] = fmaxf(acc, 0.f);
    __syncthreads();
    if (tid < NC && logit_off >= 0) {
        float a2 = b2[tid];
        #pragma unroll 8
        for (int k = 0; k < HID; k++) a2 += sh[k] * W2[tid * HID + k];
        out[logit_off + g * NC + tid] = a2;
    }
}

// ---------------------------------------------------------------------------
extern "C" void kernel_launch(void* const* d_in, const int* in_sizes, int n_in,
                              void* d_out, int out_size) {
    const float* x   = (const float*)d_in[0];
    const float* nw  = (const float*)d_in[1];
    const float* ew  = (const float*)d_in[2];
    const float* fw  = (const float*)d_in[3];
    const float* v   = (const float*)d_in[4];
    const float* W1  = (const float*)d_in[5];
    const float* b1  = (const float*)d_in[6];
    const float* W2  = (const float*)d_in[7];
    const float* b2  = (const float*)d_in[8];
    const int*   ei  = (const int*)d_in[9];
    const int*   fc  = (const int*)d_in[10];
    const int*   bid = (const int*)d_in[11];
    float* out = (float*)d_out;

    int flat_off, logit_off;
    if (out_size >= GG * NC + GG * FLATW) { logit_off = 0; flat_off = GG * NC; }
    else if (out_size >= GG * FLATW)      { logit_off = -1; flat_off = 0; }
    else                                  { logit_off = 0; flat_off = -1; }

    k_init<<<NH_B + Z_B + H_B, 256>>>(x, nw, v, ei, fc, bid);
    k_prefix<<<1, 32>>>();
    k_scatter<<<(MM + 255) / 256, 256>>>(ei, fc, bid, ew, fw);
    k_ecc<<<MAXCH, TPB>>>();
    k_tail<<<GG, HID>>>(W1, b1, W2, b2, out, flat_off, logit_off);
}

// round 8
// speedup vs baseline: 3.5558x; 2.1793x over previous
#include <cuda_runtime.h>

// Problem constants
#define NN 16000
#define EE 48000
#define FF 32000
#define GG 32
#define DD 64
#define BB 32
#define MM (NN + EE + FF)
#define HID 256
#define NC 10
#define FLATW (BB * DD)   // 2048

// ecc tiling
#define CS    128
#define ECC_Y 4
#define TPB   256
#define MAXCH ((MM + CS - 1) / CS + GG)   // 782

#define GPQ 4             // graphs per gemm1 block

// Device scratch
__device__ float g_nh[NN * DD];
__device__ int4  g_items[MM];
__device__ int   g_hist[GG];          // zero-init; re-zeroed by k_gemm2 each run
__device__ int   g_off[GG + 1];
__device__ int   g_cursor[GG];
__device__ int   g_nch;
__device__ int4  g_chunks[MAXCH];
__device__ float g_acc[GG * BB * DD]; // DIFFERENCE-domain accumulators
__device__ float g_h[GG * HID];

// Sigmoid band constants: c = e^(-200/31)
#define SIGA 6.4516129f
#define C1f  1.577973e-3f
#define C2f  2.490000e-6f
#define C3f  3.929150e-9f

// ---------------------------------------------------------------------------
// Fused: nh (float4) + g_acc zero (float4) + graph histogram
#define NH_B 1000   // NN*16/256
#define Z_B  64     // GG*BB*DD/4/256
#define H_B  375    // MM/256

__global__ void k_init(const float* __restrict__ x, const float* __restrict__ nw,
                       const float* __restrict__ v,
                       const int* __restrict__ ei, const int* __restrict__ fc,
                       const int* __restrict__ bid) {
    __shared__ int sh[GG];
    int b = blockIdx.x, tid = threadIdx.x;
    if (b < NH_B) {
        int t = b * 256 + tid;            // < NN*16
        int n = t >> 4, c4 = t & 15;
        const float4* vv = (const float4*)v;
        float4 v0 = vv[c4], v1 = vv[16 + c4], v2 = vv[32 + c4];
        float x0 = x[n * 3], x1 = x[n * 3 + 1], x2 = x[n * 3 + 2];
        float w = nw[n];
        float4 r;
        r.x = (x0 * v0.x + x1 * v1.x + x2 * v2.x) * w;
        r.y = (x0 * v0.y + x1 * v1.y + x2 * v2.y) * w;
        r.z = (x0 * v0.z + x1 * v1.z + x2 * v2.z) * w;
        r.w = (x0 * v0.w + x1 * v1.w + x2 * v2.w) * w;
        ((float4*)g_nh)[t] = r;
    } else if (b < NH_B + Z_B) {
        int t = (b - NH_B) * 256 + tid;
        ((float4*)g_acc)[t] = make_float4(0.f, 0.f, 0.f, 0.f);
    } else {
        if (tid < GG) sh[tid] = 0;
        __syncthreads();
        int t = (b - NH_B - Z_B) * 256 + tid;
        if (t < MM) {
            int g;
            if (t < NN)           g = bid[t];
            else if (t < NN + EE) g = bid[ei[t - NN]];
            else                  g = bid[fc[t - NN - EE]];
            atomicAdd(&sh[g], 1);
        }
        __syncthreads();
        if (tid < GG && sh[tid] > 0) atomicAdd(&g_hist[tid], sh[tid]);
    }
}

// Warp-parallel prefix + chunk-table builder (1 block, 32 threads)
__global__ void k_prefix() {
    int g = threadIdx.x;
    int cnt = g_hist[g];
    int v = cnt;
    #pragma unroll
    for (int s = 1; s < 32; s <<= 1) {
        int t = __shfl_up_sync(0xFFFFFFFFu, v, s);
        if (g >= s) v += t;
    }
    int off = v - cnt;
    g_off[g] = off;
    g_cursor[g] = off;
    if (g == 31) g_off[GG] = v;

    int nch = (cnt + CS - 1) / CS;
    int c = nch;
    #pragma unroll
    for (int s = 1; s < 32; s <<= 1) {
        int t = __shfl_up_sync(0xFFFFFFFFu, c, s);
        if (g >= s) c += t;
    }
    int cbase = c - nch;
    if (g == 31) g_nch = c;
    for (int j = 0; j < nch; j++) {
        int st = off + j * CS;
        int en = min(st + CS, off + cnt);
        g_chunks[cbase + j] = make_int4(g, st, en, 0);
    }
}

__global__ void k_scatter(const int* __restrict__ ei, const int* __restrict__ fc,
                          const int* __restrict__ bid,
                          const float* __restrict__ ew, const float* __restrict__ fw) {
    __shared__ int scnt[GG];
    __shared__ int sbase[GG];
    int tid = threadIdx.x;
    if (tid < GG) scnt[tid] = 0;
    __syncthreads();
    int t = blockIdx.x * blockDim.x + tid;
    int g = 0, lr = 0;
    int4 it = make_int4(0, 0, 0, 0);
    bool valid = (t < MM);
    if (valid) {
        if (t < NN) {
            g = bid[t];
            it = make_int4(t, t, t, __float_as_int(1.0f));
        } else if (t < NN + EE) {
            int e = t - NN;
            int a = ei[e], b = ei[EE + e];
            g = bid[a];
            it = make_int4(a, b, a, __float_as_int(-ew[e]));
        } else {
            int q = t - NN - EE;
            int a = fc[q], b = fc[FF + q], c = fc[2 * FF + q];
            g = bid[a];
            it = make_int4(a, b, c, __float_as_int(fw[q]));
        }
        lr = atomicAdd(&scnt[g], 1);
    }
    __syncthreads();
    if (tid < GG && scnt[tid] > 0) sbase[tid] = atomicAdd(&g_cursor[tid], scnt[tid]);
    __syncthreads();
    if (valid) g_items[sbase[g] + lr] = it;
}

// ECC kernel, difference-domain: 5 conflict-free deltas/item-dim, no atomics,
// exact sigmoids via 1 exp + 4 fast-div (MUFU pipe).
__global__ void __launch_bounds__(TPB, 6) k_ecc() {
    int bidx = blockIdx.x;
    if (bidx >= g_nch) return;
    int4 ck = g_chunks[bidx];
    int g = ck.x, start = ck.y, end = ck.z;

    __shared__ float band[ECC_Y * BB * DD];   // 32KB private (lane,dim) columns

    int tid = threadIdx.x;
    int d = tid & 63, y = tid >> 6;

    for (int i = tid; i < ECC_Y * BB * DD; i += TPB) band[i] = 0.f;
    __syncthreads();

    float* bcol = band + y * (BB * DD) + d;

    for (int i = start + y; i < end; i += ECC_Y) {
        int4 it = g_items[i];                  // broadcast across 64 dim-threads
        float s  = (it.w < 0) ? -1.f : 1.f;
        float wa = fabsf(__int_as_float(it.w));
        float h0 = g_nh[it.x * DD + d];
        float h1 = g_nh[it.y * DD + d];
        float h2 = g_nh[it.z * DD + d];
        float h  = fmaxf(h0, fmaxf(h1, h2)) * wa;

        float f  = (h + 1.0f) * 15.5f;         // bump coordinate
        float bf = ceilf(f - 2.0f);            // band rows bf..bf+3
        int blo  = (int)bf;

        // s_k = sigmoid(SIGA*(blo+k-f)) = 1/(1+E*c^k), E = e^{SIGA*(f-blo)}
        float E  = __expf((f - bf) * SIGA);
        float s0 = __fdividef(1.f, 1.f + E);
        float s1 = __fdividef(1.f, 1.f + E * C1f);
        float s2 = __fdividef(1.f, 1.f + E * C2f);
        float s3 = __fdividef(1.f, 1.f + E * C3f);

        float d0 = s * s0;
        float d1 = s * s1 - d0;
        float d2 = s * s2 - s * s1;
        float d3 = s * s3 - s * s2;
        float d4 = s - s * s3;                 // saturation delta
        float dl0 = d0, dl1 = d1, dl2 = d2, dl3 = d3, dl4 = d4;

        #pragma unroll
        for (int k = 0; k < 5; k++) {
            float dv = (k == 0) ? dl0 : (k == 1) ? dl1 : (k == 2) ? dl2
                     : (k == 3) ? dl3 : dl4;
            int j = max(blo + k, 0);
            if (j < BB) bcol[j * DD] += dv;    // private column, conflict-free
        }
    }
    __syncthreads();

    for (int i = tid; i < BB * DD; i += TPB) {
        float v = band[i] + band[BB * DD + i] + band[2 * BB * DD + i] + band[3 * BB * DD + i];
        atomicAdd(&g_acc[g * BB * DD + i], v);
    }
}

// gemm1: finalize flat (prefix over b of difference accumulators) + first layer.
// grid (8 htiles, 8 graph-quads), 256 threads. W1 traffic: 256KB/block, 16MB total.
__global__ void __launch_bounds__(256) k_gemm1(
        const float* __restrict__ W1, const float* __restrict__ b1,
        float* __restrict__ out, int flat_off) {
    __shared__ float sf[GPQ][FLATW];      // 32KB
    __shared__ float ss[GPQ][4][DD];      // 4KB
    int ht = blockIdx.x, gq = blockIdx.y;
    int tid = threadIdx.x;
    int d = tid & 63, q = tid >> 6;

    float vals[GPQ][8];
    #pragma unroll
    for (int gi = 0; gi < GPQ; gi++) {
        int g = gq * GPQ + gi;
        float run = 0.f;
        #pragma unroll
        for (int k = 0; k < 8; k++) {
            run += g_acc[(g * BB + q * 8 + k) * DD + d];
            vals[gi][k] = run;
        }
        ss[gi][q][d] = run;
    }
    __syncthreads();
    #pragma unroll
    for (int gi = 0; gi < GPQ; gi++) {
        float offp = 0.f;
        for (int r = 0; r < q; r++) offp += ss[gi][r][d];
        #pragma unroll
        for (int k = 0; k < 8; k++) {
            float fv = offp + vals[gi][k];
            sf[gi][(q * 8 + k) * DD + d] = fv;
            if (ht == 0 && flat_off >= 0)
                out[flat_off + (gq * GPQ + gi) * FLATW + (q * 8 + k) * DD + d] = fv;
        }
    }
    __syncthreads();

    int row_l = tid >> 3, lane8 = tid & 7;
    int row = ht * 32 + row_l;
    const float4* w1v = (const float4*)(W1 + row * FLATW);
    float acc0 = 0.f, acc1 = 0.f, acc2 = 0.f, acc3 = 0.f;
    #pragma unroll 4
    for (int j = 0; j < 64; j++) {
        float4 w = w1v[j * 8 + lane8];
        float4 a = ((const float4*)sf[0])[j * 8 + lane8];
        float4 b = ((const float4*)sf[1])[j * 8 + lane8];
        float4 c = ((const float4*)sf[2])[j * 8 + lane8];
        float4 e = ((const float4*)sf[3])[j * 8 + lane8];
        acc0 += w.x * a.x + w.y * a.y + w.z * a.z + w.w * a.w;
        acc1 += w.x * b.x + w.y * b.y + w.z * b.z + w.w * b.w;
        acc2 += w.x * c.x + w.y * c.y + w.z * c.z + w.w * c.w;
        acc3 += w.x * e.x + w.y * e.y + w.z * e.z + w.w * e.w;
    }
    #pragma unroll
    for (int sft = 4; sft >= 1; sft >>= 1) {
        acc0 += __shfl_down_sync(0xFFFFFFFFu, acc0, sft, 8);
        acc1 += __shfl_down_sync(0xFFFFFFFFu, acc1, sft, 8);
        acc2 += __shfl_down_sync(0xFFFFFFFFu, acc2, sft, 8);
        acc3 += __shfl_down_sync(0xFFFFFFFFu, acc3, sft, 8);
    }
    if (lane8 == 0) {
        float bb = b1[row];
        int gb = gq * GPQ;
        g_h[(gb + 0) * HID + row] = fmaxf(acc0 + bb, 0.f);
        g_h[(gb + 1) * HID + row] = fmaxf(acc1 + bb, 0.f);
        g_h[(gb + 2) * HID + row] = fmaxf(acc2 + bb, 0.f);
        g_h[(gb + 3) * HID + row] = fmaxf(acc3 + bb, 0.f);
    }
}

// gemm2: logits = h @ W2^T + b2.  One block, 320 threads. Also resets g_hist.
__global__ void k_gemm2(const float* __restrict__ W2, const float* __restrict__ b2,
                        float* __restrict__ out, int logit_off) {
    __shared__ float sh[GG][HID + 1];     // padded: conflict-free column reads
    __shared__ float sw[NC * HID];
    int tid = threadIdx.x;                // 320
    for (int i = tid; i < GG * HID; i += 320) sh[i >> 8][i & 255] = g_h[i];
    for (int i = tid; i < NC * HID; i += 320) sw[i] = W2[i];
    __syncthreads();
    int c = tid >> 5, g = tid & 31;       // c in 0..9
    float acc = b2[c];
    #pragma unroll 8
    for (int k = 0; k < HID; k++) acc += sh[g][k] * sw[c * HID + k];
    if (logit_off >= 0) out[logit_off + g * NC + c] = acc;
    if (tid < GG) g_hist[tid] = 0;        // reset for next replay
}

// ---------------------------------------------------------------------------
extern "C" void kernel_launch(void* const* d_in, const int* in_sizes, int n_in,
                              void* d_out, int out_size) {
    const float* x   = (const float*)d_in[0];
    const float* nw  = (const float*)d_in[1];
    const float* ew  = (const float*)d_in[2];
    const float* fw  = (const float*)d_in[3];
    const float* v   = (const float*)d_in[4];
    const float* W1  = (const float*)d_in[5];
    const float* b1  = (const float*)d_in[6];
    const float* W2  = (const float*)d_in[7];
    const float* b2  = (const float*)d_in[8];
    const int*   ei  = (const int*)d_in[9];
    const int*   fc  = (const int*)d_in[10];
    const int*   bid = (const int*)d_in[11];
    float* out = (float*)d_out;

    int flat_off, logit_off;
    if (out_size >= GG * NC + GG * FLATW) { logit_off = 0; flat_off = GG * NC; }
    else if (out_size >= GG * FLATW)      { logit_off = -1; flat_off = 0; }
    else                                  { logit_off = 0; flat_off = -1; }

    k_init<<<NH_B + Z_B + H_B, 256>>>(x, nw, v, ei, fc, bid);
    k_prefix<<<1, 32>>>();
    k_scatter<<<(MM + 255) / 256, 256>>>(ei, fc, bid, ew, fw);
    k_ecc<<<MAXCH, TPB>>>();
    k_gemm1<<<dim3(8, GG / GPQ), 256>>>(W1, b1, out, flat_off);
    k_gemm2<<<1, 320>>>(W2, b2, out, logit_off);
}

// round 9
// speedup vs baseline: 3.9976x; 1.1243x over previous
#include <cuda_runtime.h>

// Problem constants
#define NN 16000
#define EE 48000
#define FF 32000
#define GG 32
#define DD 64
#define BB 32
#define MM (NN + EE + FF)
#define HID 256
#define NC 10
#define FLATW (BB * DD)   // 2048

// ecc tiling
#define CS    128
#define ECC_Y 4
#define TPB   256
#define MAXCH ((MM + CS - 1) / CS + GG)   // 782
#define STR   39           // band column stride (floats): 3 low pad + 32 + 4 high pad
#define GPQ   4            // graphs per gemm1 block

// Sigmoid band constants (SIGA = 200/31)
#define C1f   1.577980e-3f   // e^{-SIGA}
#define C2f   2.490021e-6f   // e^{-2 SIGA}
#define EXP2K 9.3077108f     // SIGA * log2(e)

// Device scratch (zero-initialized at load; resets maintained by k_gemm2)
__device__ float g_nh[NN * DD];
__device__ int4  g_items[MM];
__device__ int   g_hist[GG];
__device__ int   g_cursor2[GG];
__device__ float g_acc[GG * BB * DD];   // difference-domain accumulators
__device__ float g_h[GG * HID];

// ---------------------------------------------------------------------------
// Fused: nh (float4) + g_acc zero (float4) + graph histogram
#define NH_B 1000   // NN*16/256
#define Z_B  64     // GG*BB*DD/4/256
#define H_B  375    // ceil(MM/256)

__global__ void k_init(const float* __restrict__ x, const float* __restrict__ nw,
                       const float* __restrict__ v,
                       const int* __restrict__ ei, const int* __restrict__ fc,
                       const int* __restrict__ bid) {
    __shared__ int sh[GG];
    int b = blockIdx.x, tid = threadIdx.x;
    if (b < NH_B) {
        int t = b * 256 + tid;            // < NN*16
        int n = t >> 4, c4 = t & 15;
        const float4* vv = (const float4*)v;
        float4 v0 = vv[c4], v1 = vv[16 + c4], v2 = vv[32 + c4];
        float x0 = x[n * 3], x1 = x[n * 3 + 1], x2 = x[n * 3 + 2];
        float w = nw[n];
        float4 r;
        r.x = (x0 * v0.x + x1 * v1.x + x2 * v2.x) * w;
        r.y = (x0 * v0.y + x1 * v1.y + x2 * v2.y) * w;
        r.z = (x0 * v0.z + x1 * v1.z + x2 * v2.z) * w;
        r.w = (x0 * v0.w + x1 * v1.w + x2 * v2.w) * w;
        ((float4*)g_nh)[t] = r;
    } else if (b < NH_B + Z_B) {
        int t = (b - NH_B) * 256 + tid;
        ((float4*)g_acc)[t] = make_float4(0.f, 0.f, 0.f, 0.f);
    } else {
        if (tid < GG) sh[tid] = 0;
        __syncthreads();
        int t = (b - NH_B - Z_B) * 256 + tid;
        if (t < MM) {
            int g;
            if (t < NN)           g = bid[t];
            else if (t < NN + EE) g = bid[ei[t - NN]];
            else                  g = bid[fc[t - NN - EE]];
            atomicAdd(&sh[g], 1);
        }
        __syncthreads();
        if (tid < GG && sh[tid] > 0) atomicAdd(&g_hist[tid], sh[tid]);
    }
}

// Warp-wide inclusive scan over 32 lanes
__device__ __forceinline__ int wscan(int v, int lane) {
    #pragma unroll
    for (int s = 1; s < 32; s <<= 1) {
        int t = __shfl_up_sync(0xFFFFFFFFu, v, s);
        if (lane >= s) v += t;
    }
    return v;
}

// Counting-sort scatter; offsets computed by in-block warp scan of g_hist.
__global__ void k_scatter(const int* __restrict__ ei, const int* __restrict__ fc,
                          const int* __restrict__ bid,
                          const float* __restrict__ ew, const float* __restrict__ fw) {
    __shared__ int scnt[GG];
    __shared__ int sbase[GG];
    __shared__ int soff[GG];
    int tid = threadIdx.x;
    if (tid < 32) {
        int cnt = g_hist[tid];
        int v = wscan(cnt, tid);
        soff[tid] = v - cnt;
        scnt[tid] = 0;
    }
    __syncthreads();
    int t = blockIdx.x * blockDim.x + tid;
    int g = 0, lr = 0;
    int4 it = make_int4(0, 0, 0, 0);
    bool valid = (t < MM);
    if (valid) {
        if (t < NN) {
            g = bid[t];
            int tb = t << 8;
            it = make_int4(tb, tb, tb, __float_as_int(1.0f));
        } else if (t < NN + EE) {
            int e = t - NN;
            int a = ei[e], b = ei[EE + e];
            g = bid[a];
            it = make_int4(a << 8, b << 8, a << 8, __float_as_int(-ew[e]));
        } else {
            int q = t - NN - EE;
            int a = fc[q], b = fc[FF + q], c = fc[2 * FF + q];
            g = bid[a];
            it = make_int4(a << 8, b << 8, c << 8, __float_as_int(fw[q]));
        }
        lr = atomicAdd(&scnt[g], 1);
    }
    __syncthreads();
    if (tid < GG && scnt[tid] > 0)
        sbase[tid] = soff[tid] + atomicAdd(&g_cursor2[tid], scnt[tid]);
    __syncthreads();
    if (valid) g_items[sbase[g] + lr] = it;
}

// ECC kernel: self-resolved chunks, transposed padded band, 3 sigmoids, 4 deltas.
__global__ void __launch_bounds__(TPB) k_ecc() {
    __shared__ float band[TPB * STR];       // 39936 B
    __shared__ int   sck[3];                // {g, start, end}

    int tid = threadIdx.x;
    float4* b4 = (float4*)band;
    for (int i = tid; i < TPB * STR / 4; i += TPB) b4[i] = make_float4(0.f, 0.f, 0.f, 0.f);

    if (tid < 32) {
        int cnt = g_hist[tid];
        int v = wscan(cnt, tid);
        int off = v - cnt;
        int nch = (cnt + CS - 1) / CS;
        int c = wscan(nch, tid);
        int cb = c - nch;
        int bx = blockIdx.x;
        bool own = (bx >= cb) && (bx < cb + nch);
        unsigned m = __ballot_sync(0xFFFFFFFFu, own);
        if (m == 0) {
            if (tid == 0) { sck[0] = 0; sck[1] = 0; sck[2] = 0; }
        } else {
            int src  = __ffs(m) - 1;
            int offg = __shfl_sync(0xFFFFFFFFu, off, src);
            int cbg  = __shfl_sync(0xFFFFFFFFu, cb, src);
            int cntg = __shfl_sync(0xFFFFFFFFu, cnt, src);
            if (tid == 0) {
                int st = offg + (bx - cbg) * CS;
                sck[0] = src; sck[1] = st; sck[2] = min(st + CS, offg + cntg);
            }
        }
    }
    __syncthreads();
    int g = sck[0], start = sck[1], end = sck[2];
    if (start >= end) return;

    int d = tid & 63, y = tid >> 6;
    const char* nb = (const char*)g_nh + d * 4;
    float* col = band + tid * STR;

    for (int i = start + y; i < end; i += ECC_Y) {
        int4 it = g_items[i];
        float s  = (it.w < 0) ? -1.f : 1.f;
        float wa = fabsf(__int_as_float(it.w));
        float h0 = *(const float*)(nb + it.x);
        float h1 = *(const float*)(nb + it.y);
        float h2 = *(const float*)(nb + it.z);
        float h  = fmaxf(h0, fmaxf(h1, h2)) * wa;

        float f  = fmaf(h, 15.5f, 15.5f);        // bump coordinate
        float bf = ceilf(f - 1.5f);              // band rows bf..bf+2
        int   p  = min(max((int)bf, -3), 31) + 3;// physical base row (pads absorb ends)
        float E  = exp2f((f - bf) * EXP2K);      // e^{SIGA*(f-bf)}
        float s0 = __fdividef(s, 1.f + E);       // s * sigmoid(row bf)
        float s1 = __fdividef(s, 1.f + E * C1f);
        float s2 = __fdividef(s, 1.f + E * C2f);

        float* a = col + p;
        a[0] += s0;
        a[1] += s1 - s0;
        a[2] += s2 - s1;
        a[3] += s  - s2;                          // saturation delta
    }
    __syncthreads();

    float* acc = g_acc + g * (BB * DD);
    for (int i = tid; i < BB * DD; i += TPB) {
        int b = i >> 6, dd = i & 63;
        float v = 0.f;
        #pragma unroll
        for (int y2 = 0; y2 < ECC_Y; y2++) {
            const float* c2 = band + (y2 * 64 + dd) * STR;
            v += c2[b + 3];
            if (b == 0) v += c2[0] + c2[1] + c2[2];  // low pad folds into row 0
        }
        atomicAdd(&acc[i], v);
    }
}

// gemm1: finalize flat (prefix over b) + first layer. grid (16 htiles, 8 quads).
__global__ void __launch_bounds__(256) k_gemm1(
        const float* __restrict__ W1, const float* __restrict__ b1,
        float* __restrict__ out, int flat_off) {
    __shared__ float sf[GPQ][FLATW];      // 32KB
    __shared__ float ss[GPQ][4][DD];
    int ht = blockIdx.x, gq = blockIdx.y;
    int tid = threadIdx.x;
    int d = tid & 63, q = tid >> 6;

    float vals[GPQ][8];
    #pragma unroll
    for (int gi = 0; gi < GPQ; gi++) {
        int g = gq * GPQ + gi;
        float run = 0.f;
        #pragma unroll
        for (int k = 0; k < 8; k++) {
            run += g_acc[(g * BB + q * 8 + k) * DD + d];
            vals[gi][k] = run;
        }
        ss[gi][q][d] = run;
    }
    __syncthreads();
    #pragma unroll
    for (int gi = 0; gi < GPQ; gi++) {
        float offp = 0.f;
        for (int r = 0; r < q; r++) offp += ss[gi][r][d];
        #pragma unroll
        for (int k = 0; k < 8; k++) {
            float fv = offp + vals[gi][k];
            sf[gi][(q * 8 + k) * DD + d] = fv;
            if (ht == 0 && flat_off >= 0)
                out[flat_off + (gq * GPQ + gi) * FLATW + (q * 8 + k) * DD + d] = fv;
        }
    }
    __syncthreads();

    int row_l = tid >> 4, lane = tid & 15;
    int row = ht * 16 + row_l;
    const float4* w1v = (const float4*)(W1 + row * FLATW);
    float a0 = 0.f, a1 = 0.f, a2 = 0.f, a3 = 0.f;
    #pragma unroll 4
    for (int j = 0; j < 32; j++) {
        float4 w = w1v[j * 16 + lane];
        float4 fa = ((const float4*)sf[0])[j * 16 + lane];
        float4 fb = ((const float4*)sf[1])[j * 16 + lane];
        float4 fc2 = ((const float4*)sf[2])[j * 16 + lane];
        float4 fe = ((const float4*)sf[3])[j * 16 + lane];
        a0 += w.x * fa.x + w.y * fa.y + w.z * fa.z + w.w * fa.w;
        a1 += w.x * fb.x + w.y * fb.y + w.z * fb.z + w.w * fb.w;
        a2 += w.x * fc2.x + w.y * fc2.y + w.z * fc2.z + w.w * fc2.w;
        a3 += w.x * fe.x + w.y * fe.y + w.z * fe.z + w.w * fe.w;
    }
    #pragma unroll
    for (int sft = 8; sft >= 1; sft >>= 1) {
        a0 += __shfl_down_sync(0xFFFFFFFFu, a0, sft, 16);
        a1 += __shfl_down_sync(0xFFFFFFFFu, a1, sft, 16);
        a2 += __shfl_down_sync(0xFFFFFFFFu, a2, sft, 16);
        a3 += __shfl_down_sync(0xFFFFFFFFu, a3, sft, 16);
    }
    if (lane == 0) {
        float bb = b1[row];
        int gb = gq * GPQ;
        g_h[(gb + 0) * HID + row] = fmaxf(a0 + bb, 0.f);
        g_h[(gb + 1) * HID + row] = fmaxf(a1 + bb, 0.f);
        g_h[(gb + 2) * HID + row] = fmaxf(a2 + bb, 0.f);
        g_h[(gb + 3) * HID + row] = fmaxf(a3 + bb, 0.f);
    }
}

// gemm2: logits = h @ W2^T + b2. One block, 320 threads. Resets hist/cursor.
__global__ void k_gemm2(const float* __restrict__ W2, const float* __restrict__ b2,
                        float* __restrict__ out, int logit_off) {
    __shared__ float sh[GG][HID + 1];
    __shared__ float sw[NC * HID];
    int tid = threadIdx.x;                // 320
    for (int i = tid; i < GG * HID; i += 320) sh[i >> 8][i & 255] = g_h[i];
    for (int i = tid; i < NC * HID; i += 320) sw[i] = W2[i];
    __syncthreads();
    int c = tid >> 5, g = tid & 31;       // c in 0..9
    float acc = b2[c];
    #pragma unroll 8
    for (int k = 0; k < HID; k++) acc += sh[g][k] * sw[c * HID + k];
    if (logit_off >= 0) out[logit_off + g * NC + c] = acc;
    if (tid < GG) { g_hist[tid] = 0; g_cursor2[tid] = 0; }   // reset for next replay
}

// ---------------------------------------------------------------------------
extern "C" void kernel_launch(void* const* d_in, const int* in_sizes, int n_in,
                              void* d_out, int out_size) {
    const float* x   = (const float*)d_in[0];
    const float* nw  = (const float*)d_in[1];
    const float* ew  = (const float*)d_in[2];
    const float* fw  = (const float*)d_in[3];
    const float* v   = (const float*)d_in[4];
    const float* W1  = (const float*)d_in[5];
    const float* b1  = (const float*)d_in[6];
    const float* W2  = (const float*)d_in[7];
    const float* b2  = (const float*)d_in[8];
    const int*   ei  = (const int*)d_in[9];
    const int*   fc  = (const int*)d_in[10];
    const int*   bid = (const int*)d_in[11];
    float* out = (float*)d_out;

    int flat_off, logit_off;
    if (out_size >= GG * NC + GG * FLATW) { logit_off = 0; flat_off = GG * NC; }
    else if (out_size >= GG * FLATW)      { logit_off = -1; flat_off = 0; }
    else                                  { logit_off = 0; flat_off = -1; }

    k_init<<<NH_B + Z_B + H_B, 256>>>(x, nw, v, ei, fc, bid);
    k_scatter<<<(MM + 255) / 256, 256>>>(ei, fc, bid, ew, fw);
    k_ecc<<<MAXCH, TPB>>>();
    k_gemm1<<<dim3(16, GG / GPQ), 256>>>(W1, b1, out, flat_off);
    k_gemm2<<<1, 320>>>(W2, b2, out, logit_off);
}